// round 15
// baseline (speedup 1.0000x reference)
#include <cuda_runtime.h>
#include <cuda_fp16.h>
#include <cstdint>

#define MAXN 100096

__device__ unsigned char g_ind0[MAXN];
__device__ unsigned char g_ind1[MAXN];
__device__ volatile unsigned int g_bar;

// f16 x f16 -> f32 mma
__device__ __forceinline__ void mma_f16(float* c, const unsigned* a, const unsigned* b) {
    asm volatile(
        "mma.sync.aligned.m16n8k16.row.col.f32.f16.f16.f32 "
        "{%0,%1,%2,%3},{%4,%5,%6,%7},{%8,%9},{%0,%1,%2,%3};\n"
        : "+f"(c[0]), "+f"(c[1]), "+f"(c[2]), "+f"(c[3])
        : "r"(a[0]), "r"(a[1]), "r"(a[2]), "r"(a[3]), "r"(b[0]), "r"(b[1]));
}

// fp32 pair -> packed fp16x2 (RN)
__device__ __forceinline__ unsigned cvt2h(float2 f) {
    unsigned h;
    asm("cvt.rn.f16x2.f32 %0, %1, %2;" : "=r"(h) : "f"(f.y), "f"(f.x));
    return h;
}

// packed fp16x2 -> float2
__device__ __forceinline__ float2 h2f2(unsigned u) {
    __half2 h = *(__half2*)&u;
    return __half22float2(h);
}

// Software grid barrier: grid sized from the occupancy API so all blocks are
// co-resident -> safe.
__device__ __forceinline__ void grid_bar(unsigned nblocks) {
    __syncthreads();
    if (threadIdx.x == 0) {
        __threadfence();
        unsigned old = atomicAdd((unsigned*)&g_bar, 1u);
        unsigned target = (old / nblocks + 1u) * nblocks;
        while (g_bar < target) { }
        __threadfence();
    }
    __syncthreads();
}

// smem layout (u32 units), per 256-thread block (8 warps)
#define BF_OFF    0        // 9216 : B-ext frags fp16 (18 n-tiles x 8 kc x 32 x uint2)
#define RED_OFF   9216     // 1664 : per-warp extras, 8 warps x 16 nodes x pitch 13
#define GBUF_OFF  10880    // 1152 : per-warp g01/b2, 8 warps x 16 nodes x pitch 9
#define BRS_OFF   12032    // 128
#define QS_OFF    12160    // 512
#define CHS_OFF   12672    // 8
#define SMEM_U32  12680    // 50720 bytes

// Persistent kernel; warp-autonomous 16-node groups with STATIC round-robin
// assignment (no work-steal atomic — same-address L2 atomics serialize at
// ~27cyc/op and were the ~85us floor). 256 threads/block, 3 blocks/SM.
__global__ void __launch_bounds__(256, 3) fused_kernel(
    const float* __restrict__ feat, const float* __restrict__ Wr,
    const float* __restrict__ br, const float* __restrict__ rl,
    const float* __restrict__ rr,
    const int* __restrict__ d0, int E0, const int* __restrict__ d1, int E1,
    float* __restrict__ out, int N)
{
    extern __shared__ unsigned smem_u[];
    unsigned* BF = smem_u + BF_OFF;
    float* red  = (float*)(smem_u + RED_OFF);
    float* gbuf = (float*)(smem_u + GBUF_OFF);
    float* br_s = (float*)(smem_u + BRS_OFF);
    float* q_s  = (float*)(smem_u + QS_OFF);
    float* ch_s = (float*)(smem_u + CHS_OFF);

    const int tid  = threadIdx.x;
    const int lane = tid & 31;
    const int warp = tid >> 5;          // 0..7
    const unsigned nb = gridDim.x;

    // ---- phase 0: zero flags
    for (int i = blockIdx.x * 256 + tid; i < MAXN / 4; i += nb * 256) {
        ((unsigned*)g_ind0)[i] = 0u;
        ((unsigned*)g_ind1)[i] = 0u;
    }
    grid_bar(nb);

    // ---- phase 1: mark flags
    for (int i = blockIdx.x * 256 + tid; i < E0 + E1; i += nb * 256) {
        if (i < E0) g_ind0[d0[i]] = 1;
        else        g_ind1[d1[i - E0]] = 1;
    }

    // ---- prologue (overlaps other blocks' marking)
    if (tid < 128) br_s[tid] = br[tid];
    __syncthreads();
    for (int p = tid; p < 512; p += 256) {
        int h = p >> 7, k = p & 127;
        float s = 0.f;
        #pragma unroll 4
        for (int t = 0; t < 32; t++)
            s += __ldg(&Wr[(h * 32 + t) * 128 + k]) * __ldg(&rr[h * 32 + t]);
        q_s[p] = s;
    }
    if (tid < 4) {
        float s = 0.f;
        for (int t = 0; t < 32; t++)
            s += __ldg(&br[tid * 32 + t]) * __ldg(&rr[tid * 32 + t]);
        ch_s[tid] = s;
    }
    __syncthreads();

    // B-ext fragments (fp16): t'<128 Wr; 128-131 q_h; 132-135 rr head-masked;
    // 136-139 rl head-masked; 140-143 zero. mma fragment layout.
    for (int i = tid; i < 9216; i += 256) {
        int j  = i & 1;
        int ln = (i >> 1) & 31;
        int kc = (i >> 6) & 7;
        int nt = i >> 9;
        int tp = nt * 8 + (ln >> 2);
        int k0 = kc * 16 + (ln & 3) * 2 + j * 8;
        float v[2];
        #pragma unroll
        for (int e = 0; e < 2; e++) {
            int k = k0 + e;
            float x;
            if (tp < 128)      x = __ldg(&Wr[tp * 128 + k]);
            else if (tp < 132) x = q_s[(tp - 128) * 128 + k];
            else if (tp < 136) x = ((k >> 5) == (tp - 132)) ? __ldg(&rr[k]) : 0.f;
            else if (tp < 140) x = ((k >> 5) == (tp - 136)) ? __ldg(&rl[k]) : 0.f;
            else               x = 0.f;
            v[e] = x;
        }
        BF[i] = cvt2h(make_float2(v[0], v[1]));
    }

    grid_bar(nb);   // marking done everywhere; B frags visible

    // ---- main loop: static round-robin over 16-node groups (NO atomics)
    const unsigned T16 = (unsigned)((N + 15) >> 4);
    const unsigned wgid = blockIdx.x * 8u + (unsigned)warp;
    const unsigned nwg  = nb * 8u;
    const uint2* bp = ((const uint2*)BF) + lane;
    float* red_w  = red  + warp * 208;   // 16 nodes x pitch 13
    float* gbuf_w = gbuf + warp * 144;   // 16 nodes x pitch 9
    const int r = lane >> 2;
    const int q = lane & 3;

    for (unsigned g = wgid; g < T16; g += nwg) {
        long n0 = (long)g * 16 + r;
        long n1 = n0 + 8;
        long c0n = n0 > N - 1 ? N - 1 : n0;
        long c1n = n1 > N - 1 ? N - 1 : n1;
        const float2* f0p = (const float2*)(feat + c0n * 128) + q;
        const float2* f1p = (const float2*)(feat + c1n * 128) + q;

        // ---- A -> fp16 registers; 4 batches of 8 independent LDG (MLP=8)
        uint4 Ah[8];
        {
            float2 t[8];
            #pragma unroll
            for (int kc = 0; kc < 8; kc++) t[kc] = __ldg(f0p + kc * 8);
            #pragma unroll
            for (int kc = 0; kc < 8; kc++) Ah[kc].x = cvt2h(t[kc]);
            #pragma unroll
            for (int kc = 0; kc < 8; kc++) t[kc] = __ldg(f0p + kc * 8 + 4);
            #pragma unroll
            for (int kc = 0; kc < 8; kc++) Ah[kc].z = cvt2h(t[kc]);
            #pragma unroll
            for (int kc = 0; kc < 8; kc++) t[kc] = __ldg(f1p + kc * 8);
            #pragma unroll
            for (int kc = 0; kc < 8; kc++) Ah[kc].y = cvt2h(t[kc]);
            #pragma unroll
            for (int kc = 0; kc < 8; kc++) t[kc] = __ldg(f1p + kc * 8 + 4);
            #pragma unroll
            for (int kc = 0; kc < 8; kc++) Ah[kc].w = cvt2h(t[kc]);
        }

        // ---- extras MMA (n-tiles 16,17)
        {
            float ax[4] = {0.f, 0.f, 0.f, 0.f};
            float ay[4] = {0.f, 0.f, 0.f, 0.f};
            #pragma unroll
            for (int kc = 0; kc < 8; kc++) {
                uint2 b16 = bp[(16 * 8 + kc) * 32];
                uint2 b17 = bp[(17 * 8 + kc) * 32];
                mma_f16(ax, (const unsigned*)&Ah[kc], (const unsigned*)&b16);
                mma_f16(ay, (const unsigned*)&Ah[kc], (const unsigned*)&b17);
            }
            int cidx = q * 2;
            float s0 = ax[0], s1 = ax[1], s2 = ax[2], s3 = ax[3];
            if (cidx < 4) {
                float cA = ch_s[cidx], cB = ch_s[cidx + 1];
                s0 += cA; s1 += cB; s2 += cA; s3 += cB;
            }
            red_w[r * 13 + cidx]           = s0;
            red_w[r * 13 + cidx + 1]       = s1;
            red_w[(r + 8) * 13 + cidx]     = s2;
            red_w[(r + 8) * 13 + cidx + 1] = s3;
            if (cidx < 4) {
                red_w[r * 13 + 8 + cidx]       = ay[0];
                red_w[r * 13 + 9 + cidx]       = ay[1];
                red_w[(r + 8) * 13 + 8 + cidx] = ay[2];
                red_w[(r + 8) * 13 + 9 + cidx] = ay[3];
            }
        }
        __syncwarp();

        // ---- softmax: lanes 0-15, node = lane
        if (lane < 16) {
            long ng = (long)g * 16 + lane;
            int cn = ng < N ? (int)ng : N - 1;
            float i0 = (float)g_ind0[cn];
            float i1 = (float)g_ind1[cn];
            const float* rw = &red_w[lane * 13];
            float sv[4], sf[4], al[4];
            #pragma unroll
            for (int h = 0; h < 4; h++) {
                sv[h] = rw[h]; sf[h] = rw[4 + h]; al[h] = rw[8 + h];
            }
            float bta[3][4];
            #pragma unroll
            for (int jr = 0; jr < 3; jr++) {
                float x[4];
                #pragma unroll
                for (int h = 0; h < 4; h++) {
                    float ar = (jr == 0) ? i0 * sv[h] : (jr == 1) ? i1 * sv[h] : sf[h];
                    float xx = al[h] + ar;
                    x[h] = (xx > 0.f) ? xx : 0.2f * xx;
                }
                float mx = fmaxf(fmaxf(x[0], x[1]), fmaxf(x[2], x[3]));
                float e0 = __expf(x[0] - mx), e1 = __expf(x[1] - mx);
                float e2 = __expf(x[2] - mx), e3 = __expf(x[3] - mx);
                float inv = 1.f / (e0 + e1 + e2 + e3);
                bta[jr][0] = e0 * inv; bta[jr][1] = e1 * inv;
                bta[jr][2] = e2 * inv; bta[jr][3] = e3 * inv;
            }
            #pragma unroll
            for (int h = 0; h < 4; h++) {
                gbuf_w[lane * 9 + h]     = bta[0][h] * i0 + bta[1][h] * i1;
                gbuf_w[lane * 9 + 4 + h] = bta[2][h];
            }
        }
        __syncwarp();

        // ---- outputs: 2 chunks of 8 n-tiles; MMA then immediate epilogue.
        // feat for the b2 term reconstructed from resident Ah (fp16-rounded).
        #pragma unroll
        for (int c2 = 0; c2 < 2; c2++) {
            float acc[8][4];
            #pragma unroll
            for (int i = 0; i < 8; i++)
                #pragma unroll
                for (int c = 0; c < 4; c++) acc[i][c] = 0.f;

            #pragma unroll
            for (int kc = 0; kc < 8; kc++) {
                #pragma unroll
                for (int i = 0; i < 8; i++) {
                    uint2 bb = bp[((c2 * 8 + i) * 8 + kc) * 32];
                    mma_f16(acc[i], (const unsigned*)&Ah[kc], (const unsigned*)&bb);
                }
            }

            #pragma unroll
            for (int i = 0; i < 8; i++) {
                int gnt = c2 * 8 + i;
                int head = gnt >> 2;
                int jj = gnt >> 1;
                int tc2 = gnt * 4 + q;           // float2 index; col = 2*tc2
                float2 brv = *(const float2*)&br_s[tc2 * 2];
                float2 fa = h2f2((gnt & 1) ? Ah[jj].z : Ah[jj].x);  // row r
                float2 fb = h2f2((gnt & 1) ? Ah[jj].w : Ah[jj].y);  // row r+8
                float g01a = gbuf_w[r * 9 + head];
                float b2a  = gbuf_w[r * 9 + 4 + head];
                float g01b = gbuf_w[(r + 8) * 9 + head];
                float b2b  = gbuf_w[(r + 8) * 9 + 4 + head];
                float v0 = acc[i][0] + brv.x;
                float v1 = acc[i][1] + brv.y;
                float v2 = acc[i][2] + brv.x;
                float v3 = acc[i][3] + brv.y;
                if (n0 < N) {
                    float o0 = fmaxf(fmaf(g01a, v0, b2a * fa.x), 0.f);
                    float o1 = fmaxf(fmaf(g01a, v1, b2a * fa.y), 0.f);
                    *(float2*)&out[n0 * 128 + tc2 * 2] = make_float2(o0, o1);
                }
                if (n1 < N) {
                    float o2 = fmaxf(fmaf(g01b, v2, b2b * fb.x), 0.f);
                    float o3 = fmaxf(fmaf(g01b, v3, b2b * fb.y), 0.f);
                    *(float2*)&out[n1 * 128 + tc2 * 2] = make_float2(o2, o3);
                }
            }
        }
        __syncwarp();   // red_w/gbuf_w safe for next group
    }
}

extern "C" void kernel_launch(void* const* d_in, const int* in_sizes, int n_in,
                              void* d_out, int out_size) {
    // Inputs: feat, Wl, bl, Wr, br, attn_l, attn_r, rel_attn_l, rel_attn_r,
    //         alpha, src0, dst0, src1, dst1
    const float* feat = (const float*)d_in[0];
    const float* Wr   = (const float*)d_in[3];
    const float* br   = (const float*)d_in[4];
    const float* rl   = (const float*)d_in[7];
    const float* rr   = (const float*)d_in[8];
    const int* dst0   = (const int*)d_in[11];
    const int* dst1   = (const int*)d_in[13];
    float* out        = (float*)d_out;

    const int N  = in_sizes[0] / 128;
    const int E0 = in_sizes[11];
    const int E1 = in_sizes[13];

    const int SMEM_BYTES = SMEM_U32 * 4;
    cudaFuncSetAttribute(fused_kernel,
                         cudaFuncAttributeMaxDynamicSharedMemorySize, SMEM_BYTES);
    int nsm = 148;
    cudaDeviceGetAttribute(&nsm, cudaDevAttrMultiProcessorCount, 0);
    // Size the grid from real occupancy so the software grid barrier can
    // never deadlock (all blocks co-resident by construction).
    int bpm = 1;
    cudaOccupancyMaxActiveBlocksPerMultiprocessor(&bpm, fused_kernel, 256,
                                                  SMEM_BYTES);
    if (bpm < 1) bpm = 1;
    if (bpm > 4) bpm = 4;
    int grid = nsm * bpm;
    fused_kernel<<<grid, 256, SMEM_BYTES>>>(feat, Wr, br, rl, rr,
                                            dst0, E0, dst1, E1, out, N);
}

// round 16
// speedup vs baseline: 1.1026x; 1.1026x over previous
#include <cuda_runtime.h>
#include <cuda_fp16.h>
#include <cstdint>

#define MAXN 100096

__device__ unsigned char g_ind0[MAXN];
__device__ unsigned char g_ind1[MAXN];
__device__ volatile unsigned int g_bar;

// f16 x f16 -> f32 mma
__device__ __forceinline__ void mma_f16(float* c, const unsigned* a, const unsigned* b) {
    asm volatile(
        "mma.sync.aligned.m16n8k16.row.col.f32.f16.f16.f32 "
        "{%0,%1,%2,%3},{%4,%5,%6,%7},{%8,%9},{%0,%1,%2,%3};\n"
        : "+f"(c[0]), "+f"(c[1]), "+f"(c[2]), "+f"(c[3])
        : "r"(a[0]), "r"(a[1]), "r"(a[2]), "r"(a[3]), "r"(b[0]), "r"(b[1]));
}

// fp32 pair -> packed fp16x2 (RN)
__device__ __forceinline__ unsigned cvt2h(float2 f) {
    unsigned h;
    asm("cvt.rn.f16x2.f32 %0, %1, %2;" : "=r"(h) : "f"(f.y), "f"(f.x));
    return h;
}

// packed fp16x2 -> float2
__device__ __forceinline__ float2 h2f2(unsigned u) {
    __half2 h = *(__half2*)&u;
    return __half22float2(h);
}

// Software grid barrier: grid = 1 block/SM -> all co-resident -> safe.
__device__ __forceinline__ void grid_bar(unsigned nblocks) {
    __syncthreads();
    if (threadIdx.x == 0) {
        __threadfence();
        unsigned old = atomicAdd((unsigned*)&g_bar, 1u);
        unsigned target = (old / nblocks + 1u) * nblocks;
        while (g_bar < target) { }
        __threadfence();
    }
    __syncthreads();
}

// smem layout (u32 units), per 512-thread block (16 warps)
#define BF_OFF    0        // 9216 : B-ext frags fp16 (18 n-tiles x 8 kc x 32 x uint2)
#define RED_OFF   9216     // 3328 : per-warp extras, 16 warps x 16 nodes x pitch 13
#define GBUF_OFF  12544    // 2304 : per-warp g01/b2, 16 warps x 16 nodes x pitch 9
#define BRS_OFF   14848    // 128
#define QS_OFF    14976    // 512
#define CHS_OFF   15488    // 8
#define CTR_OFF   15496    // 1 : per-block work counter
#define SMEM_U32  15500    // 62000 bytes

// Prefetch one group's 16 feat rows (16x512B = 64 lines) into L2.
// 32 lanes x 2 prefetches cover all 64 lines.
__device__ __forceinline__ void prefetch_group(const float* feat, unsigned g,
                                               int N, int lane) {
    long n = (long)g * 16 + (lane >> 1);
    if (n > N - 1) n = N - 1;
    const char* base = (const char*)(feat + n * 128) + (lane & 1) * 256;
    asm volatile("prefetch.global.L2 [%0];" :: "l"(base));
    asm volatile("prefetch.global.L2 [%0];" :: "l"(base + 128));
}

// Persistent kernel; warp-autonomous 16-node groups. Work distribution:
// contiguous per-block range + smem atomic counter (perfect intra-block
// balance, no global atomic serialization). Each warp pulls its NEXT group
// before processing the current one and L2-prefetches its rows, converting
// the A-load from DRAM-latency to L2-latency.
__global__ void __launch_bounds__(512, 1) fused_kernel(
    const float* __restrict__ feat, const float* __restrict__ Wr,
    const float* __restrict__ br, const float* __restrict__ rl,
    const float* __restrict__ rr,
    const int* __restrict__ d0, int E0, const int* __restrict__ d1, int E1,
    float* __restrict__ out, int N)
{
    extern __shared__ unsigned smem_u[];
    unsigned* BF = smem_u + BF_OFF;
    float* red  = (float*)(smem_u + RED_OFF);
    float* gbuf = (float*)(smem_u + GBUF_OFF);
    float* br_s = (float*)(smem_u + BRS_OFF);
    float* q_s  = (float*)(smem_u + QS_OFF);
    float* ch_s = (float*)(smem_u + CHS_OFF);
    unsigned* s_ctr = smem_u + CTR_OFF;

    const int tid  = threadIdx.x;
    const int lane = tid & 31;
    const int warp = tid >> 5;          // 0..15
    const unsigned nb = gridDim.x;

    // ---- phase 0: zero flags; reset per-block counter
    for (int i = blockIdx.x * 512 + tid; i < MAXN / 4; i += nb * 512) {
        ((unsigned*)g_ind0)[i] = 0u;
        ((unsigned*)g_ind1)[i] = 0u;
    }
    if (tid == 0) s_ctr[0] = 0u;
    grid_bar(nb);

    // ---- phase 1: mark flags
    for (int i = blockIdx.x * 512 + tid; i < E0 + E1; i += nb * 512) {
        if (i < E0) g_ind0[d0[i]] = 1;
        else        g_ind1[d1[i - E0]] = 1;
    }

    // ---- prologue (overlaps other blocks' marking)
    if (tid < 128) br_s[tid] = br[tid];
    __syncthreads();
    if (tid < 512) {
        int h = tid >> 7, k = tid & 127;
        float s = 0.f;
        #pragma unroll 4
        for (int t = 0; t < 32; t++)
            s += __ldg(&Wr[(h * 32 + t) * 128 + k]) * __ldg(&rr[h * 32 + t]);
        q_s[tid] = s;
    }
    if (tid < 4) {
        float s = 0.f;
        for (int t = 0; t < 32; t++)
            s += __ldg(&br[tid * 32 + t]) * __ldg(&rr[tid * 32 + t]);
        ch_s[tid] = s;
    }
    __syncthreads();

    // B-ext fragments (fp16): t'<128 Wr; 128-131 q_h; 132-135 rr head-masked;
    // 136-139 rl head-masked; 140-143 zero. mma fragment layout.
    for (int i = tid; i < 9216; i += 512) {
        int j  = i & 1;
        int ln = (i >> 1) & 31;
        int kc = (i >> 6) & 7;
        int nt = i >> 9;
        int tp = nt * 8 + (ln >> 2);
        int k0 = kc * 16 + (ln & 3) * 2 + j * 8;
        float v[2];
        #pragma unroll
        for (int e = 0; e < 2; e++) {
            int k = k0 + e;
            float x;
            if (tp < 128)      x = __ldg(&Wr[tp * 128 + k]);
            else if (tp < 132) x = q_s[(tp - 128) * 128 + k];
            else if (tp < 136) x = ((k >> 5) == (tp - 132)) ? __ldg(&rr[k]) : 0.f;
            else if (tp < 140) x = ((k >> 5) == (tp - 136)) ? __ldg(&rl[k]) : 0.f;
            else               x = 0.f;
            v[e] = x;
        }
        BF[i] = cvt2h(make_float2(v[0], v[1]));
    }

    grid_bar(nb);   // marking done everywhere; B frags + s_ctr visible

    // ---- main loop: per-block contiguous range, smem-counter pulled
    const unsigned T16 = (unsigned)((N + 15) >> 4);
    const unsigned gstart = (unsigned)(((unsigned long long)T16 * blockIdx.x) / nb);
    const unsigned gend   = (unsigned)(((unsigned long long)T16 * (blockIdx.x + 1)) / nb);
    const uint2* bp = ((const uint2*)BF) + lane;
    float* red_w  = red  + warp * 208;   // 16 nodes x pitch 13
    float* gbuf_w = gbuf + warp * 144;   // 16 nodes x pitch 9
    const int r = lane >> 2;
    const int q = lane & 3;

    // pull next group index (smem atomic on lane 0, broadcast)
    auto pull = [&]() -> unsigned {
        unsigned idx;
        if (lane == 0) idx = atomicAdd(s_ctr, 1u);
        idx = __shfl_sync(0xffffffffu, idx, 0);
        unsigned g = gstart + idx;
        return (g < gend) ? g : 0xffffffffu;
    };

    unsigned g_cur = pull();
    while (g_cur != 0xffffffffu) {
        unsigned g_next = pull();
        if (g_next != 0xffffffffu) prefetch_group(feat, g_next, N, lane);

        const unsigned g = g_cur;
        long n0 = (long)g * 16 + r;
        long n1 = n0 + 8;
        long c0n = n0 > N - 1 ? N - 1 : n0;
        long c1n = n1 > N - 1 ? N - 1 : n1;
        const float2* f0p = (const float2*)(feat + c0n * 128) + q;
        const float2* f1p = (const float2*)(feat + c1n * 128) + q;

        // ---- A -> fp16 registers; 4 batches of 8 independent LDG (MLP=8)
        uint4 Ah[8];
        {
            float2 t[8];
            #pragma unroll
            for (int kc = 0; kc < 8; kc++) t[kc] = __ldg(f0p + kc * 8);
            #pragma unroll
            for (int kc = 0; kc < 8; kc++) Ah[kc].x = cvt2h(t[kc]);
            #pragma unroll
            for (int kc = 0; kc < 8; kc++) t[kc] = __ldg(f0p + kc * 8 + 4);
            #pragma unroll
            for (int kc = 0; kc < 8; kc++) Ah[kc].z = cvt2h(t[kc]);
            #pragma unroll
            for (int kc = 0; kc < 8; kc++) t[kc] = __ldg(f1p + kc * 8);
            #pragma unroll
            for (int kc = 0; kc < 8; kc++) Ah[kc].y = cvt2h(t[kc]);
            #pragma unroll
            for (int kc = 0; kc < 8; kc++) t[kc] = __ldg(f1p + kc * 8 + 4);
            #pragma unroll
            for (int kc = 0; kc < 8; kc++) Ah[kc].w = cvt2h(t[kc]);
        }

        // ---- extras MMA (n-tiles 16,17)
        {
            float ax[4] = {0.f, 0.f, 0.f, 0.f};
            float ay[4] = {0.f, 0.f, 0.f, 0.f};
            #pragma unroll
            for (int kc = 0; kc < 8; kc++) {
                uint2 b16 = bp[(16 * 8 + kc) * 32];
                uint2 b17 = bp[(17 * 8 + kc) * 32];
                mma_f16(ax, (const unsigned*)&Ah[kc], (const unsigned*)&b16);
                mma_f16(ay, (const unsigned*)&Ah[kc], (const unsigned*)&b17);
            }
            int cidx = q * 2;
            float s0 = ax[0], s1 = ax[1], s2 = ax[2], s3 = ax[3];
            if (cidx < 4) {
                float cA = ch_s[cidx], cB = ch_s[cidx + 1];
                s0 += cA; s1 += cB; s2 += cA; s3 += cB;
            }
            red_w[r * 13 + cidx]           = s0;
            red_w[r * 13 + cidx + 1]       = s1;
            red_w[(r + 8) * 13 + cidx]     = s2;
            red_w[(r + 8) * 13 + cidx + 1] = s3;
            if (cidx < 4) {
                red_w[r * 13 + 8 + cidx]       = ay[0];
                red_w[r * 13 + 9 + cidx]       = ay[1];
                red_w[(r + 8) * 13 + 8 + cidx] = ay[2];
                red_w[(r + 8) * 13 + 9 + cidx] = ay[3];
            }
        }
        __syncwarp();

        // ---- softmax: lanes 0-15, node = lane
        if (lane < 16) {
            long ng = (long)g * 16 + lane;
            int cn = ng < N ? (int)ng : N - 1;
            float i0 = (float)g_ind0[cn];
            float i1 = (float)g_ind1[cn];
            const float* rw = &red_w[lane * 13];
            float sv[4], sf[4], al[4];
            #pragma unroll
            for (int h = 0; h < 4; h++) {
                sv[h] = rw[h]; sf[h] = rw[4 + h]; al[h] = rw[8 + h];
            }
            float bta[3][4];
            #pragma unroll
            for (int jr = 0; jr < 3; jr++) {
                float x[4];
                #pragma unroll
                for (int h = 0; h < 4; h++) {
                    float ar = (jr == 0) ? i0 * sv[h] : (jr == 1) ? i1 * sv[h] : sf[h];
                    float xx = al[h] + ar;
                    x[h] = (xx > 0.f) ? xx : 0.2f * xx;
                }
                float mx = fmaxf(fmaxf(x[0], x[1]), fmaxf(x[2], x[3]));
                float e0 = __expf(x[0] - mx), e1 = __expf(x[1] - mx);
                float e2 = __expf(x[2] - mx), e3 = __expf(x[3] - mx);
                float inv = 1.f / (e0 + e1 + e2 + e3);
                bta[jr][0] = e0 * inv; bta[jr][1] = e1 * inv;
                bta[jr][2] = e2 * inv; bta[jr][3] = e3 * inv;
            }
            #pragma unroll
            for (int h = 0; h < 4; h++) {
                gbuf_w[lane * 9 + h]     = bta[0][h] * i0 + bta[1][h] * i1;
                gbuf_w[lane * 9 + 4 + h] = bta[2][h];
            }
        }
        __syncwarp();

        // ---- outputs: 2 chunks of 8 n-tiles; MMA then immediate epilogue.
        // feat for the b2 term reconstructed from resident Ah (fp16-rounded).
        #pragma unroll
        for (int c2 = 0; c2 < 2; c2++) {
            float acc[8][4];
            #pragma unroll
            for (int i = 0; i < 8; i++)
                #pragma unroll
                for (int c = 0; c < 4; c++) acc[i][c] = 0.f;

            #pragma unroll
            for (int kc = 0; kc < 8; kc++) {
                #pragma unroll
                for (int i = 0; i < 8; i++) {
                    uint2 bb = bp[((c2 * 8 + i) * 8 + kc) * 32];
                    mma_f16(acc[i], (const unsigned*)&Ah[kc], (const unsigned*)&bb);
                }
            }

            #pragma unroll
            for (int i = 0; i < 8; i++) {
                int gnt = c2 * 8 + i;
                int head = gnt >> 2;
                int jj = gnt >> 1;
                int tc2 = gnt * 4 + q;           // float2 index; col = 2*tc2
                float2 brv = *(const float2*)&br_s[tc2 * 2];
                float2 fa = h2f2((gnt & 1) ? Ah[jj].z : Ah[jj].x);  // row r
                float2 fb = h2f2((gnt & 1) ? Ah[jj].w : Ah[jj].y);  // row r+8
                float g01a = gbuf_w[r * 9 + head];
                float b2a  = gbuf_w[r * 9 + 4 + head];
                float g01b = gbuf_w[(r + 8) * 9 + head];
                float b2b  = gbuf_w[(r + 8) * 9 + 4 + head];
                float v0 = acc[i][0] + brv.x;
                float v1 = acc[i][1] + brv.y;
                float v2 = acc[i][2] + brv.x;
                float v3 = acc[i][3] + brv.y;
                if (n0 < N) {
                    float o0 = fmaxf(fmaf(g01a, v0, b2a * fa.x), 0.f);
                    float o1 = fmaxf(fmaf(g01a, v1, b2a * fa.y), 0.f);
                    *(float2*)&out[n0 * 128 + tc2 * 2] = make_float2(o0, o1);
                }
                if (n1 < N) {
                    float o2 = fmaxf(fmaf(g01b, v2, b2b * fb.x), 0.f);
                    float o3 = fmaxf(fmaf(g01b, v3, b2b * fb.y), 0.f);
                    *(float2*)&out[n1 * 128 + tc2 * 2] = make_float2(o2, o3);
                }
            }
        }
        __syncwarp();   // red_w/gbuf_w safe for next group

        g_cur = g_next;
    }
}

extern "C" void kernel_launch(void* const* d_in, const int* in_sizes, int n_in,
                              void* d_out, int out_size) {
    // Inputs: feat, Wl, bl, Wr, br, attn_l, attn_r, rel_attn_l, rel_attn_r,
    //         alpha, src0, dst0, src1, dst1
    const float* feat = (const float*)d_in[0];
    const float* Wr   = (const float*)d_in[3];
    const float* br   = (const float*)d_in[4];
    const float* rl   = (const float*)d_in[7];
    const float* rr   = (const float*)d_in[8];
    const int* dst0   = (const int*)d_in[11];
    const int* dst1   = (const int*)d_in[13];
    float* out        = (float*)d_out;

    const int N  = in_sizes[0] / 128;
    const int E0 = in_sizes[11];
    const int E1 = in_sizes[13];

    const int SMEM_BYTES = SMEM_U32 * 4;
    cudaFuncSetAttribute(fused_kernel,
                         cudaFuncAttributeMaxDynamicSharedMemorySize, SMEM_BYTES);
    int nsm = 148;
    cudaDeviceGetAttribute(&nsm, cudaDevAttrMultiProcessorCount, 0);
    int T16 = (N + 15) >> 4;
    int grid = nsm < T16 ? nsm : T16;
    fused_kernel<<<grid, 512, SMEM_BYTES>>>(feat, Wr, br, rl, rr,
                                            dst0, E0, dst1, E1, out, N);
}